// round 8
// baseline (speedup 1.0000x reference)
#include <cuda_runtime.h>

#define NEGV (-9e15f)

constexpr int N  = 512;
constexpr int F  = 64;
constexpr int BS = 8;
constexpr int WARPS = 8;              // 8 rows per CTA
constexpr int THREADS = WARPS * 32;
constexpr int OUT_OFF = BS * N * F;   // 262144
constexpr float L2E = 1.4426950408889634f;

__global__ __launch_bounds__(THREADS)
void gat_kernel(const float* __restrict__ x,    // [8,512,1]
                const int*   __restrict__ adj,  // [512,512]
                const float* __restrict__ ext,  // [8,512,8]
                const float* __restrict__ side, // [8,512,1]
                const float* __restrict__ W,    // [1,64]
                const float* __restrict__ a,    // [128,1]
                const float* __restrict__ WS,   // [1,64]
                const float* __restrict__ aS,   // [128,1]
                const float* __restrict__ WQ,   // [2,16]
                const float* __restrict__ WK,   // [2,16]
                const float* __restrict__ WV,   // [1,64]
                float* __restrict__ out)        // [2,8,512,64]
{
    __shared__ float  s_c[8];                   // scalar contractions (4..7 pre-scaled by L2E)
    __shared__ float  s_xs[N];                  // x_j     (batch-shared)
    __shared__ float  s_sd[N];                  // side_j
    __shared__ float4 s_ext[N][2];              // ext[b]  (16KB, batch-shared)
    __shared__ unsigned short s_list[WARPS][N]; // compacted j per row
    // per-row constants (written by Pass A owner warp)
    __shared__ float s_mL[WARPS], s_t1[WARPS], s_t2[WARPS];
    __shared__ float s_qa0[WARPS], s_qa1[WARPS], s_mei[WARPS];
    __shared__ int   s_cnt[WARPS], s_deg[WARPS];
    __shared__ int   s_coff[WARPS + 1];
    __shared__ float s_part[WARPS][WARPS][4];   // [consumer warp][row][den,ynum,znum,_]

    const int tid  = threadIdx.x;
    const int lane = tid & 31;
    const int w    = tid >> 5;
    const int row  = blockIdx.x * WARPS + w;    // b*512 + i (CTA: one batch)
    const int b    = row >> 9;
    const int i    = row & 511;
    const int ibase = (blockIdx.x * WARPS) & 511;  // i_local of row 0 in CTA

    // ---- prologue: warp w computes scalar contraction w ----
    {
        float val;
        if (w < 4) {
            const float* Wp = (w < 2) ? W : WS;
            const float* ap = (w < 2) ? a : aS;
            const int off   = (w & 1) ? 64 : 0;
            val = Wp[lane] * ap[off + lane] + Wp[lane + 32] * ap[off + 32 + lane];
        } else {
            const int l16 = lane & 15;
            const float* q = WQ + (((w == 5) || (w == 7)) ? 16 : 0);
            const float* k = WK + ((w >= 6) ? 16 : 0);
            // 0.5 (dup half-lanes) * 0.25 (1/sqrt(16)) * L2E (fold log2e into qk)
            val = q[l16] * k[l16] * (0.125f * L2E);
        }
        #pragma unroll
        for (int o = 16; o; o >>= 1) val += __shfl_xor_sync(0xffffffffu, val, o);
        if (lane == 0) s_c[w] = val;
    }

    // ---- CTA-cooperative staging ----
    const float* xb = x    + (b << 9);
    const float* sb = side + (b << 9);
    const float4* extb4 = (const float4*)(ext + ((size_t)(b << 9) * 8));
    #pragma unroll
    for (int idx = tid; idx < N; idx += THREADS) {
        s_xs[idx] = xb[idx];
        s_sd[idx] = sb[idx];
    }
    #pragma unroll
    for (int idx = tid; idx < N * 2; idx += THREADS)
        ((float4*)s_ext)[idx] = extb4[idx];
    if (tid < WARPS * WARPS) {
        s_part[tid >> 3][tid & 7][0] = 0.f;
        s_part[tid >> 3][tid & 7][1] = 0.f;
        s_part[tid >> 3][tid & 7][2] = 0.f;
    }
    __syncthreads();   // #1

    const float c1 = s_c[0], c2 = s_c[1], cs1 = s_c[2], cs2 = s_c[3];
    const float A0L = s_c[4], B0L = s_c[5], A1L = s_c[6], B1L = s_c[7];

    const float xi = s_xs[i];
    const float si = s_sd[i];
    const float t1 = xi * c1;
    const float t2 = si * cs1;

    const int* ar = adj + (i << 9);

    // ---- Pass A: logits, row max, ballot compaction into own row list ----
    float lmax = NEGV;
    int   cnt  = 0;
    #pragma unroll
    for (int jj = 0; jj < N / 32; jj++) {
        int   j  = jj * 32 + lane;
        float e  = fmaf(c2,  s_xs[j], t1);  e  = fmaxf(e,  0.2f * e);  // leakyrelu
        float es = fmaf(cs2, s_sd[j], t2);  es = fmaxf(es, 0.2f * es);
        float s  = e + es;
        bool act = (ar[j] > 0) && (s > 0.f);
        unsigned mk = __ballot_sync(0xffffffffu, act);
        if (act) {
            int pos = cnt + __popc(mk & ((1u << lane) - 1u));
            s_list[w][pos] = (unsigned short)j;
            lmax = fmaxf(lmax, s);
        }
        cnt += __popc(mk);
    }
    #pragma unroll
    for (int o = 16; o; o >>= 1)
        lmax = fmaxf(lmax, __shfl_xor_sync(0xffffffffu, lmax, o));

    // Degenerate row (no active j): reference softmax uniform over ALL 512 j
    // (p = exp(NEG-NEG) = 1). Write identity list, p handled by deg flag.
    int deg = (cnt == 0);
    if (deg) {
        #pragma unroll
        for (int jj = 0; jj < N / 32; jj++)
            s_list[w][jj * 32 + lane] = (unsigned short)(jj * 32 + lane);
        cnt = N;
    }
    if (lane == 0) {
        float4 ea = s_ext[i & 511][0], eb = s_ext[i & 511][1];
        s_mL [w] = lmax * L2E;
        s_t1 [w] = t1;
        s_t2 [w] = t2;
        s_qa0[w] = xi * A0L;
        s_qa1[w] = xi * A1L;
        s_mei[w] = (ea.x+ea.y+ea.z+ea.w+eb.x+eb.y+eb.z+eb.w) * 0.125f;
        s_cnt[w] = cnt;
        s_deg[w] = deg;
    }
    __syncthreads();   // #2

    if (tid == 0) {
        int o = 0;
        #pragma unroll
        for (int k = 0; k < WARPS; k++) { s_coff[k] = o; o += (s_cnt[k] + 31) >> 5; }
        s_coff[WARPS] = o;
    }
    __syncthreads();   // #3

    // ---- Pass B: uniform 32-entry chunks, static round-robin over warps ----
    {
        const int tot = s_coff[WARPS];
        int   cur = -1, ccnt = 0, cdeg = 0;
        float mL = 0.f, rt1 = 0.f, rt2 = 0.f, qa0 = 0.f, qa1 = 0.f, mei = 0.f;
        float ei0=0,ei1=0,ei2=0,ei3=0,ei4=0,ei5=0,ei6=0,ei7=0;
        float aden = 0.f, ayn = 0.f, azn = 0.f;

        for (int g = w; g < tot; g += WARPS) {
            int r = 0;
            #pragma unroll
            for (int k = 1; k < WARPS; k++) r += (g >= s_coff[k]);
            if (r != cur) {
                if (cur >= 0) {   // flush previous row's partials (warp-reduce)
                    #pragma unroll
                    for (int o = 16; o; o >>= 1) {
                        aden += __shfl_xor_sync(0xffffffffu, aden, o);
                        ayn  += __shfl_xor_sync(0xffffffffu, ayn,  o);
                        azn  += __shfl_xor_sync(0xffffffffu, azn,  o);
                    }
                    if (lane == 0) {
                        s_part[w][cur][0] = aden;
                        s_part[w][cur][1] = ayn;
                        s_part[w][cur][2] = azn;
                    }
                    aden = ayn = azn = 0.f;
                }
                cur = r;
                mL  = s_mL[r];  rt1 = s_t1[r];  rt2 = s_t2[r];
                qa0 = s_qa0[r]; qa1 = s_qa1[r]; mei = s_mei[r];
                ccnt = s_cnt[r]; cdeg = s_deg[r];
                int il = (ibase + r) & 511;
                float4 ea = s_ext[il][0], eb = s_ext[il][1];
                ei0=ea.x; ei1=ea.y; ei2=ea.z; ei3=ea.w;
                ei4=eb.x; ei5=eb.y; ei6=eb.z; ei7=eb.w;
            }
            int t = ((g - s_coff[r]) << 5) + lane;
            bool valid = (t < ccnt);
            int  j  = valid ? (int)s_list[r][t] : 0;
            float xj = s_xs[j];
            float sdj = s_sd[j];
            float e  = fmaf(c2,  xj,  rt1);  e  = fmaxf(e,  0.2f * e);
            float es = fmaf(cs2, sdj, rt2);  es = fmaxf(es, 0.2f * es);
            float sL = fmaf(e + es, L2E, -mL);
            float p  = cdeg ? 1.f : exp2f(sL);
            p = valid ? p : 0.f;
            aden += p;
            ayn  += p * xj;
            float qk0 = fmaf(xj, B0L, qa0);     // log2e pre-folded
            float qk1 = fmaf(xj, B1L, qa1);
            float4 fa = s_ext[j][0];
            float4 fb = s_ext[j][1];
            float s8 = 0.f, wn = 0.f, df, pf;
            #define INNER(EIF, EJF) \
                df = fmaf(EIF, qk0, (EJF) * qk1); \
                pf = (df > 0.f) ? exp2f(df) : 0.f; \
                s8 += pf;  wn = fmaf(pf, EIF, wn);
            INNER(ei0, fa.x) INNER(ei1, fa.y) INNER(ei2, fa.z) INNER(ei3, fa.w)
            INNER(ei4, fb.x) INNER(ei5, fb.y) INNER(ei6, fb.z) INNER(ei7, fb.w)
            #undef INNER
            // all-nonpositive inner row -> reference softmax uniform -> mean(ei)
            azn += p * ((s8 > 0.f) ? __fdividef(wn, s8) : mei);
        }
        if (cur >= 0) {
            #pragma unroll
            for (int o = 16; o; o >>= 1) {
                aden += __shfl_xor_sync(0xffffffffu, aden, o);
                ayn  += __shfl_xor_sync(0xffffffffu, ayn,  o);
                azn  += __shfl_xor_sync(0xffffffffu, azn,  o);
            }
            if (lane == 0) {
                s_part[w][cur][0] = aden;
                s_part[w][cur][1] = ayn;
                s_part[w][cur][2] = azn;
            }
        }
    }
    __syncthreads();   // #4

    // ---- output: warp w owns row w; sum partials across the 8 warps ----
    float D = 0.f, Y = 0.f, Z = 0.f;
    #pragma unroll
    for (int k = 0; k < WARPS; k++) {
        D += s_part[k][w][0];
        Y += s_part[k][w][1];
        Z += s_part[k][w][2];
    }
    const float y = Y / D;
    const float z = Z / D;

    size_t base = (size_t)row * F + lane;
    float v;
    v = y * W[lane];        out[base]                = (v > 0.f) ? v : expm1f(v);
    v = y * W[lane + 32];   out[base + 32]           = (v > 0.f) ? v : expm1f(v);
    v = z * WV[lane];       out[OUT_OFF + base]      = (v > 0.f) ? v : expm1f(v);
    v = z * WV[lane + 32];  out[OUT_OFF + base + 32] = (v > 0.f) ? v : expm1f(v);
}

extern "C" void kernel_launch(void* const* d_in, const int* in_sizes, int n_in,
                              void* d_out, int out_size) {
    const float* input = (const float*)d_in[0];
    const int*   adj   = (const int*)  d_in[1];
    const float* ext   = (const float*)d_in[2];
    const float* side  = (const float*)d_in[3];
    const float* W     = (const float*)d_in[4];
    const float* a     = (const float*)d_in[5];
    const float* WS    = (const float*)d_in[6];
    const float* aS    = (const float*)d_in[7];
    const float* WQ    = (const float*)d_in[8];
    const float* WK    = (const float*)d_in[9];
    const float* WV    = (const float*)d_in[10];
    float* out = (float*)d_out;

    gat_kernel<<<(BS * N) / WARPS, THREADS>>>(input, adj, ext, side,
                                              W, a, WS, aS, WQ, WK, WV, out);
}

// round 9
// speedup vs baseline: 1.2495x; 1.2495x over previous
#include <cuda_runtime.h>

#define NEGV (-9e15f)

constexpr int N  = 512;
constexpr int F  = 64;
constexpr int BS = 8;
constexpr int WARPS = 8;              // 1 warp per row, 8 rows per CTA
constexpr int THREADS = WARPS * 32;
constexpr int OUT_OFF = BS * N * F;   // 262144
constexpr float L2E = 1.4426950408889634f;

__device__ __forceinline__ float ex2(float v) {
    float r;
    asm("ex2.approx.f32 %0, %1;" : "=f"(r) : "f"(v));
    return r;
}

__global__ __launch_bounds__(THREADS)
void gat_kernel(const float* __restrict__ x,    // [8,512,1]
                const int*   __restrict__ adj,  // [512,512]
                const float* __restrict__ ext,  // [8,512,8]
                const float* __restrict__ side, // [8,512,1]
                const float* __restrict__ W,    // [1,64]
                const float* __restrict__ a,    // [128,1]
                const float* __restrict__ WS,   // [1,64]
                const float* __restrict__ aS,   // [128,1]
                const float* __restrict__ WQ,   // [2,16]
                const float* __restrict__ WK,   // [2,16]
                const float* __restrict__ WV,   // [1,64]
                float* __restrict__ out)        // [2,8,512,64]
{
    // NOTE: all 8 scalars are pre-scaled by log2(e) so every softmax exp is a
    // bare ex2.approx. Valid because leakyrelu commutes with positive scaling
    // and sign tests (s>0, df>0) are scale-invariant.
    __shared__ float s_c[8];
    __shared__ float s_xs[N];                   // x_j     (batch-shared)
    __shared__ float s_sd[N];                   // side_j
    __shared__ float          s_sc[WARPS][N];   // compacted logits (log2 units)
    __shared__ unsigned short s_j [WARPS][N];   // compacted j

    const int tid  = threadIdx.x;
    const int lane = tid & 31;
    const int w    = tid >> 5;
    const int row  = blockIdx.x * WARPS + w;    // b*512 + i (CTA: one batch)
    const int b    = row >> 9;
    const int i    = row & 511;

    // ---- prologue: warp w computes scalar contraction w (scaled by L2E) ----
    {
        float val;
        if (w < 4) {
            const float* Wp = (w < 2) ? W : WS;
            const float* ap = (w < 2) ? a : aS;
            const int off   = (w & 1) ? 64 : 0;
            val = Wp[lane] * ap[off + lane] + Wp[lane + 32] * ap[off + 32 + lane];
        } else {
            const int l16 = lane & 15;
            const float* q = WQ + (((w == 5) || (w == 7)) ? 16 : 0);
            const float* k = WK + ((w >= 6) ? 16 : 0);
            // 0.5 (dup half-lanes) * 0.25 (1/sqrt(16))
            val = q[l16] * k[l16] * 0.125f;
        }
        #pragma unroll
        for (int o = 16; o; o >>= 1) val += __shfl_xor_sync(0xffffffffu, val, o);
        if (lane == 0) s_c[w] = val * L2E;
    }

    // ---- CTA-cooperative staging of x_j / side_j ----
    const float* xb = x    + (b << 9);
    const float* sb = side + (b << 9);
    #pragma unroll
    for (int idx = tid; idx < N; idx += THREADS) {
        s_xs[idx] = xb[idx];
        s_sd[idx] = sb[idx];
    }
    __syncthreads();

    const float c1 = s_c[0], c2 = s_c[1], cs1 = s_c[2], cs2 = s_c[3];
    const float A0 = s_c[4], B0 = s_c[5], A1  = s_c[6], B1  = s_c[7];

    const float xi = s_xs[i];
    const float si = s_sd[i];
    const float t1 = xi * c1;       // log2-scaled
    const float t2 = si * cs1;
    const float xiA0 = xi * A0;     // log2-scaled
    const float xiA1 = xi * A1;

    const float* extb = ext + ((size_t)(b << 9) * 8);
    float ei[8];
    {
        const float4* e4 = (const float4*)(extb + (size_t)i * 8);
        float4 ea = e4[0], eb = e4[1];
        ei[0]=ea.x; ei[1]=ea.y; ei[2]=ea.z; ei[3]=ea.w;
        ei[4]=eb.x; ei[5]=eb.y; ei[6]=eb.z; ei[7]=eb.w;
    }
    const float mean_ei = (ei[0]+ei[1]+ei[2]+ei[3]+ei[4]+ei[5]+ei[6]+ei[7]) * 0.125f;

    // ---- Pass A: vectorized (4 j's per lane), ballot compaction ----
    // List order is scrambled vs sequential j — harmless, sums are order-free.
    float lmax = NEGV;
    int   cnt  = 0;
    const int4* ar4 = (const int4*)(adj + (i << 9));
    #pragma unroll
    for (int blk = 0; blk < 4; blk++) {
        const int j0 = (blk << 7) + (lane << 2);
        int4   av = ar4[(blk << 5) + lane];
        float4 xv = *(const float4*)(s_xs + j0);   // 16B stride: conflict-free
        float4 sv = *(const float4*)(s_sd + j0);
        #pragma unroll
        for (int k = 0; k < 4; k++) {
            float xj = (k==0)?xv.x:(k==1)?xv.y:(k==2)?xv.z:xv.w;
            float sj = (k==0)?sv.x:(k==1)?sv.y:(k==2)?sv.z:sv.w;
            int   ad = (k==0)?av.x:(k==1)?av.y:(k==2)?av.z:av.w;
            float e  = fmaf(c2,  xj, t1);  e  = fmaxf(e,  0.2f * e);  // leakyrelu
            float es = fmaf(cs2, sj, t2);  es = fmaxf(es, 0.2f * es);
            float s  = e + es;                     // log2 units
            bool act = (ad > 0) && (s > 0.f);
            unsigned mk = __ballot_sync(0xffffffffu, act);
            if (act) {
                int pos = cnt + __popc(mk & ((1u << lane) - 1u));
                s_j [w][pos] = (unsigned short)(j0 + k);
                s_sc[w][pos] = s;
                lmax = fmaxf(lmax, s);
            }
            cnt += __popc(mk);
        }
    }
    #pragma unroll
    for (int o = 16; o; o >>= 1)
        lmax = fmaxf(lmax, __shfl_xor_sync(0xffffffffu, lmax, o));
    const float m = lmax;

    // Degenerate row (no active j): reference softmax is uniform over ALL j
    // (every p = exp(NEG-NEG) = 1). Identity list; p forced to 1 below.
    const bool degen = (cnt == 0);
    if (degen) {
        #pragma unroll
        for (int jj = 0; jj < N / 32; jj++) {
            int j = jj * 32 + lane;
            s_j [w][j] = (unsigned short)j;
            s_sc[w][j] = 0.f;
        }
        cnt = N;
    }

    // ---- Pass B: dense walk over compacted list ----
    float den = 0.f, ynum = 0.f, znum = 0.f;
    const unsigned short* jl = s_j [w];
    const float*          sl = s_sc[w];
    for (int t = lane; t < cnt; t += 32) {
        int   j  = jl[t];
        float p  = degen ? 1.f : ex2(sl[t] - m);
        float xj = s_xs[j];
        den  += p;
        ynum += p * xj;
        float qk0 = fmaf(xj, B0, xiA0);            // log2-scaled
        float qk1 = fmaf(xj, B1, xiA1);
        const float4* f4 = (const float4*)(extb + (size_t)j * 8);
        float4 fa = f4[0], fb = f4[1];
        float s8 = 0.f, wn = 0.f, df, pf;
        #define INNER(EIF, EJF) \
            df = fmaf(EIF, qk0, (EJF) * qk1); \
            pf = (df > 0.f) ? ex2(df) : 0.f; \
            s8 += pf;  wn = fmaf(pf, EIF, wn);
        INNER(ei[0], fa.x) INNER(ei[1], fa.y) INNER(ei[2], fa.z) INNER(ei[3], fa.w)
        INNER(ei[4], fb.x) INNER(ei[5], fb.y) INNER(ei[6], fb.z) INNER(ei[7], fb.w)
        #undef INNER
        // all-nonpositive inner row -> reference softmax uniform -> mean(ei)
        znum += p * ((s8 > 0.f) ? __fdividef(wn, s8) : mean_ei);
    }
    #pragma unroll
    for (int o = 16; o; o >>= 1) {
        den  += __shfl_xor_sync(0xffffffffu, den,  o);
        ynum += __shfl_xor_sync(0xffffffffu, ynum, o);
        znum += __shfl_xor_sync(0xffffffffu, znum, o);
    }
    const float y = __fdividef(ynum, den);
    const float z = __fdividef(znum, den);

    // ---- outputs: elu(y*W[f]), elu(z*WV[f]) ----
    size_t base = (size_t)row * F + lane;
    float v;
    v = y * W[lane];        out[base]                = (v > 0.f) ? v : expm1f(v);
    v = y * W[lane + 32];   out[base + 32]           = (v > 0.f) ? v : expm1f(v);
    v = z * WV[lane];       out[OUT_OFF + base]      = (v > 0.f) ? v : expm1f(v);
    v = z * WV[lane + 32];  out[OUT_OFF + base + 32] = (v > 0.f) ? v : expm1f(v);
}

extern "C" void kernel_launch(void* const* d_in, const int* in_sizes, int n_in,
                              void* d_out, int out_size) {
    const float* input = (const float*)d_in[0];
    const int*   adj   = (const int*)  d_in[1];
    const float* ext   = (const float*)d_in[2];
    const float* side  = (const float*)d_in[3];
    const float* W     = (const float*)d_in[4];
    const float* a     = (const float*)d_in[5];
    const float* WS    = (const float*)d_in[6];
    const float* aS    = (const float*)d_in[7];
    const float* WQ    = (const float*)d_in[8];
    const float* WK    = (const float*)d_in[9];
    const float* WV    = (const float*)d_in[10];
    float* out = (float*)d_out;

    gat_kernel<<<(BS * N) / WARPS, THREADS>>>(input, adj, ext, side,
                                              W, a, WS, aS, WQ, WK, WV, out);
}